// round 3
// baseline (speedup 1.0000x reference)
#include <cuda_runtime.h>
#include <cstdint>

// out[b,m] = einsum('bd,cd,ce,em->bm', bp, mp, CE, W)
// Re-associated (2x fewer FLOPs than reference order):
//   G1: A1[d,e] = sum_c mp[c,d]*CE[c,e]   (34.4 GFLOP, mma.sync tf32)
//   G2: Z[b,e]  = sum_d bp[b,d]*A1[d,e]   (0.27 GFLOP, SIMT split-K)
//   G3: out     = Z @ W                   (tiny)
// B=128, C=16384, E=64, M=128, all fp32.

#define C_DIM 16384
#define E_DIM 64
#define B_DIM 128
#define M_DIM 128

// ---- G1 tiling ----
#define KC     32                 // K (c) per pipeline stage
#define KITERS (C_DIM / KC)       // 512
#define AST    136                // A smem row stride in floats (128 + 8 pad)
#define BST    72                 // B smem row stride in floats (64 + 8 pad)
#define A_STG  (KC * AST)         // 4352 floats per A stage
#define B_STG  (KC * BST)         // 2304 floats per B stage
#define NSTG   4
#define B_OFF  (NSTG * A_STG)     // float offset of B region in dyn smem
#define SMEM_FLOATS (NSTG * (A_STG + B_STG))
#define SMEM_BYTES  (SMEM_FLOATS * 4)   // 106496

__device__ float g_A1  [(size_t)C_DIM * E_DIM];          // 4 MB scratch
__device__ float g_part[(size_t)128 * B_DIM * E_DIM];    // 4 MB scratch

// ---------------- helpers ----------------
__device__ __forceinline__ uint32_t smem_u32(const void* p) {
    uint32_t a;
    asm("{ .reg .u64 t; cvta.to.shared.u64 t, %1; cvt.u32.u64 %0, t; }" : "=r"(a) : "l"(p));
    return a;
}
__device__ __forceinline__ void cp16(uint32_t s, const void* g) {
    asm volatile("cp.async.cg.shared.global [%0], [%1], 16;" :: "r"(s), "l"(g) : "memory");
}
#define CP_COMMIT() asm volatile("cp.async.commit_group;" ::: "memory")
#define CP_WAIT2()  asm volatile("cp.async.wait_group 2;" ::: "memory")

__device__ __forceinline__ uint32_t t32(float x) {   // fp32 -> tf32 (round to nearest)
    uint32_t u;
    asm("cvt.rna.tf32.f32 %0, %1;" : "=r"(u) : "f"(x));
    return u;
}
__device__ __forceinline__ void mma_tf32(float* c, const uint32_t* a, const uint32_t* b) {
    asm volatile(
        "mma.sync.aligned.m16n8k8.row.col.f32.tf32.tf32.f32 "
        "{%0,%1,%2,%3}, {%4,%5,%6,%7}, {%8,%9}, {%0,%1,%2,%3};"
        : "+f"(c[0]), "+f"(c[1]), "+f"(c[2]), "+f"(c[3])
        : "r"(a[0]), "r"(a[1]), "r"(a[2]), "r"(a[3]), "r"(b[0]), "r"(b[1]));
}

// ---------------- G1: A1 = mp^T @ CE ----------------
// CTA: 128 d-rows x 64 e-cols, K=16384. 8 warps as 4(d) x 2(e); warp tile 32x32.
__device__ __forceinline__ void g1_load(uint32_t sbase, int stage, int kb, int tid,
                                        const float* __restrict__ mp,
                                        const float* __restrict__ ce, size_t D0) {
    uint32_t sA = sbase + (uint32_t)(stage * A_STG) * 4u;
    uint32_t sB = sbase + (uint32_t)(B_OFF + stage * B_STG) * 4u;
    size_t krow = (size_t)kb * KC;
#pragma unroll
    for (int i = 0; i < 4; i++) {                 // A: 32 rows x 512 B
        int q = tid + 256 * i;                    // 0..1023
        int row = q >> 5, c16 = q & 31;
        cp16(sA + (uint32_t)(row * (AST * 4) + c16 * 16),
             mp + (krow + (size_t)row) * C_DIM + D0 + (size_t)c16 * 4);
    }
#pragma unroll
    for (int i = 0; i < 2; i++) {                 // B: 32 rows x 256 B
        int q = tid + 256 * i;                    // 0..511
        int row = q >> 4, c16 = q & 15;
        cp16(sB + (uint32_t)(row * (BST * 4) + c16 * 16),
             ce + (krow + (size_t)row) * E_DIM + (size_t)c16 * 4);
    }
}

__global__ void __launch_bounds__(256, 1)
g1_mpce(const float* __restrict__ mp, const float* __restrict__ ce) {
    extern __shared__ float sm[];
    uint32_t sbase = smem_u32(sm);
    const int tid  = threadIdx.x;
    const int wid  = tid >> 5, lane = tid & 31;
    const int lq   = lane & 3, lr = lane >> 2;
    const int wm   = wid >> 1;        // 0..3 -> d offset wm*32
    const int wn   = wid & 1;         // 0..1 -> e offset wn*32
    const size_t D0 = (size_t)blockIdx.x * 128;

    float acc[2][4][4];
#pragma unroll
    for (int mf = 0; mf < 2; mf++)
#pragma unroll
        for (int nf = 0; nf < 4; nf++)
#pragma unroll
            for (int j = 0; j < 4; j++) acc[mf][nf][j] = 0.f;

    for (int s = 0; s < 3; s++) { g1_load(sbase, s, s, tid, mp, ce, D0); CP_COMMIT(); }

    for (int k = 0; k < KITERS; k++) {
        CP_WAIT2();                       // stage k resident (3 were in flight)
        __syncthreads();                  // all threads past compute of k-1
        if (k + 3 < KITERS) { g1_load(sbase, (k + 3) & 3, k + 3, tid, mp, ce, D0); CP_COMMIT(); }

        const float* Af = sm + (k & 3) * A_STG;
        const float* Bf = sm + B_OFF + (k & 3) * B_STG;

#pragma unroll
        for (int ks = 0; ks < 4; ks++) {
            const float* Ar  = Af + (ks * 8 + lq) * AST;       // k-row lq
            const float* Ar4 = Ar + 4 * AST;                   // k-row lq+4
            uint32_t au[2][4];
#pragma unroll
            for (int mf = 0; mf < 2; mf++) {
                int dw = wm * 32 + mf * 16 + lr;
                au[mf][0] = t32(Ar [dw]);
                au[mf][1] = t32(Ar [dw + 8]);
                au[mf][2] = t32(Ar4[dw]);
                au[mf][3] = t32(Ar4[dw + 8]);
            }
            const float* Br  = Bf + (ks * 8 + lq) * BST;
            const float* Br4 = Br + 4 * BST;
            uint32_t bu[4][2];
#pragma unroll
            for (int nf = 0; nf < 4; nf++) {
                int ew = wn * 32 + nf * 8 + lr;
                bu[nf][0] = t32(Br [ew]);
                bu[nf][1] = t32(Br4[ew]);
            }
#pragma unroll
            for (int mf = 0; mf < 2; mf++)
#pragma unroll
                for (int nf = 0; nf < 4; nf++)
                    mma_tf32(acc[mf][nf], au[mf], bu[nf]);
        }
    }

    // epilogue: D[r, 2lq], D[r, 2lq+1], D[r+8, 2lq], D[r+8, 2lq+1]
#pragma unroll
    for (int mf = 0; mf < 2; mf++) {
        size_t r0 = D0 + (size_t)(wm * 32 + mf * 16 + lr);
#pragma unroll
        for (int nf = 0; nf < 4; nf++) {
            int e0 = wn * 32 + nf * 8 + 2 * lq;
            *reinterpret_cast<float2*>(&g_A1[r0 * E_DIM + e0]) =
                make_float2(acc[mf][nf][0], acc[mf][nf][1]);
            *reinterpret_cast<float2*>(&g_A1[(r0 + 8) * E_DIM + e0]) =
                make_float2(acc[mf][nf][2], acc[mf][nf][3]);
        }
    }
}

// ---------------- G2: part[p] = bp[:, p-slab] @ A1[p-slab, :] ----------------
__global__ void __launch_bounds__(256)
g2_bpA1(const float* __restrict__ bp) {
    __shared__ float bps[128 * 36];   // [b][c] pad 4
    __shared__ float a1s[32 * 68];    // [c][e] pad 4
    int tid = threadIdx.x;
    int tx = tid & 15, ty = tid >> 4;     // tx -> e (4 each), ty -> b (8 each)
    size_t c0 = (size_t)blockIdx.x * 128;

    float acc[8][4];
#pragma unroll
    for (int i = 0; i < 8; i++)
#pragma unroll
        for (int j = 0; j < 4; j++) acc[i][j] = 0.f;

    for (int cc = 0; cc < 4; cc++) {
#pragma unroll
        for (int i = 0; i < 4; i++) {
            int q = tid + 256 * i;            // 1024 float4 for bp 128x32
            int row = q >> 3, c4 = q & 7;
            *reinterpret_cast<float4*>(&bps[row * 36 + c4 * 4]) =
                *reinterpret_cast<const float4*>(&bp[(size_t)row * C_DIM + c0 + cc * 32 + c4 * 4]);
        }
#pragma unroll
        for (int i = 0; i < 2; i++) {
            int q = tid + 256 * i;            // 512 float4 for A1 32x64
            int row = q >> 4, c4 = q & 15;
            *reinterpret_cast<float4*>(&a1s[row * 68 + c4 * 4]) =
                *reinterpret_cast<const float4*>(&g_A1[(c0 + cc * 32 + (size_t)row) * E_DIM + c4 * 4]);
        }
        __syncthreads();
#pragma unroll 4
        for (int c = 0; c < 32; c++) {
            float4 bv = *reinterpret_cast<const float4*>(&a1s[c * 68 + tx * 4]);
#pragma unroll
            for (int i = 0; i < 8; i++) {
                float a = bps[(ty * 8 + i) * 36 + c];
                acc[i][0] += a * bv.x; acc[i][1] += a * bv.y;
                acc[i][2] += a * bv.z; acc[i][3] += a * bv.w;
            }
        }
        __syncthreads();
    }
    float* op = g_part + (size_t)blockIdx.x * (B_DIM * E_DIM);
#pragma unroll
    for (int i = 0; i < 8; i++)
        *reinterpret_cast<float4*>(&op[(ty * 8 + i) * E_DIM + tx * 4]) =
            make_float4(acc[i][0], acc[i][1], acc[i][2], acc[i][3]);
}

// ---------------- G3: out[b,m] = sum_e (sum_p part[p][b][e]) * W[e,m] ----------------
__global__ void __launch_bounds__(128)
g3_out(const float* __restrict__ w, float* __restrict__ out) {
    __shared__ float zs[E_DIM];
    int b = blockIdx.x, t = threadIdx.x;
    if (t < E_DIM) {
        float s = 0.f;
#pragma unroll 8
        for (int p = 0; p < 128; p++)
            s += g_part[(size_t)p * (B_DIM * E_DIM) + b * E_DIM + t];
        zs[t] = s;
    }
    __syncthreads();
    float acc = 0.f;
#pragma unroll 8
    for (int e = 0; e < E_DIM; e++)
        acc += zs[e] * w[e * M_DIM + t];
    out[b * M_DIM + t] = acc;
}

// ---------------- launch ----------------
extern "C" void kernel_launch(void* const* d_in, const int* in_sizes, int n_in,
                              void* d_out, int out_size) {
    const float* bp = (const float*)d_in[0];   // [128, 16384]
    const float* mp = (const float*)d_in[1];   // [16384, 16384]
    const float* ce = (const float*)d_in[2];   // [16384, 64]
    const float* w  = (const float*)d_in[3];   // [64, 128]
    float* out = (float*)d_out;                // [128, 128]

    cudaFuncSetAttribute(g1_mpce, cudaFuncAttributeMaxDynamicSharedMemorySize, SMEM_BYTES);
    g1_mpce<<<C_DIM / 128, 256, SMEM_BYTES>>>(mp, ce);
    g2_bpA1<<<128, 256>>>(bp);
    g3_out<<<128, 128>>>(w, out);
}

// round 4
// speedup vs baseline: 1.1877x; 1.1877x over previous
#include <cuda_runtime.h>
#include <cstdint>

// out[b,m] = einsum('bd,cd,ce,em->bm', bp, mp, CE, W)
//   K0: CEt = tf32(CE)                    (one-time convert, 4 MB)
//   G1: A1h[kh][d,e] = sum_{c in half} mp[c,d]*CE[c,e]   (tf32 mma.sync, K-split x2)
//   G2: Z[b,e] = sum_d bp[b,d]*(A1h0+A1h1)[d,e]          (SIMT split-K)
//   G3: out = Z @ W
// B=128, C=16384, E=64, M=128 fp32.

#define C_DIM 16384
#define E_DIM 64
#define B_DIM 128
#define M_DIM 128
#define KHALF 8192

#define KC     16
#define KITERS (KHALF / KC)       // 512 per K-half
#define AST    136
#define BST    72
#define A_STG  (KC * AST)
#define B_STG  (KC * BST)
#define NSTG   4
#define B_OFF  (NSTG * A_STG)
#define SMEM_FLOATS (NSTG * (A_STG + B_STG))
#define SMEM_BYTES  (SMEM_FLOATS * 4)   // 53248 -> 2 CTAs/SM

#define CH ((size_t)C_DIM * E_DIM)

__device__ float    g_A1  [2 * CH];
__device__ uint32_t g_CEt [CH];
__device__ float    g_part[(size_t)128 * B_DIM * E_DIM];

__device__ __forceinline__ uint32_t smem_u32(const void* p) {
    uint32_t a;
    asm("{ .reg .u64 t; cvta.to.shared.u64 t, %1; cvt.u32.u64 %0, t; }" : "=r"(a) : "l"(p));
    return a;
}
__device__ __forceinline__ void cp16(uint32_t s, const void* g) {
    asm volatile("cp.async.cg.shared.global [%0], [%1], 16;" :: "r"(s), "l"(g) : "memory");
}
#define CP_COMMIT() asm volatile("cp.async.commit_group;" ::: "memory")
#define CP_WAIT2()  asm volatile("cp.async.wait_group 2;" ::: "memory")

__device__ __forceinline__ uint32_t t32(float x) {
    uint32_t u;
    asm("cvt.rna.tf32.f32 %0, %1;" : "=r"(u) : "f"(x));
    return u;
}
__device__ __forceinline__ void mma_tf32(float* c, const uint32_t* a, const uint32_t* b) {
    asm volatile(
        "mma.sync.aligned.m16n8k8.row.col.f32.tf32.tf32.f32 "
        "{%0,%1,%2,%3}, {%4,%5,%6,%7}, {%8,%9}, {%0,%1,%2,%3};"
        : "+f"(c[0]), "+f"(c[1]), "+f"(c[2]), "+f"(c[3])
        : "r"(a[0]), "r"(a[1]), "r"(a[2]), "r"(a[3]), "r"(b[0]), "r"(b[1]));
}

__global__ void __launch_bounds__(256) k0_cvt(const float* __restrict__ ce) {
    size_t i = ((size_t)blockIdx.x * 256 + threadIdx.x) * 4;
    float4 v = *reinterpret_cast<const float4*>(ce + i);
    uint4 o;
    o.x = t32(v.x); o.y = t32(v.y); o.z = t32(v.z); o.w = t32(v.w);
    *reinterpret_cast<uint4*>(g_CEt + i) = o;
}

__device__ __forceinline__ void g1_load(uint32_t sbase, int stage, size_t krow, int tid,
                                        const float* __restrict__ mp, size_t D0) {
    uint32_t sA = sbase + (uint32_t)(stage * A_STG) * 4u;
    uint32_t sB = sbase + (uint32_t)(B_OFF + stage * B_STG) * 4u;
#pragma unroll
    for (int i = 0; i < 2; i++) {
        int q = tid + 256 * i;
        int row = q >> 5, c16 = q & 31;
        cp16(sA + (uint32_t)(row * (AST * 4) + c16 * 16),
             mp + (krow + (size_t)row) * C_DIM + D0 + (size_t)c16 * 4);
    }
    {
        int row = tid >> 4, c16 = tid & 15;
        cp16(sB + (uint32_t)(row * (BST * 4) + c16 * 16),
             g_CEt + (krow + (size_t)row) * E_DIM + (size_t)c16 * 4);
    }
}

__global__ void __launch_bounds__(256, 2)
g1_mpce(const float* __restrict__ mp) {
    extern __shared__ float sm[];
    uint32_t sbase = smem_u32(sm);
    const int tid  = threadIdx.x;
    const int wid  = tid >> 5, lane = tid & 31;
    const int lq   = lane & 3, lr = lane >> 2;
    const int wm   = wid >> 1;
    const int wn   = wid & 1;
    const int slab = blockIdx.x & 127;
    const int kh   = blockIdx.x >> 7;
    const size_t D0 = (size_t)slab * 128;
    const size_t K0 = (size_t)kh * KHALF;

    float acc[2][4][4];
#pragma unroll
    for (int mf = 0; mf < 2; mf++)
#pragma unroll
        for (int nf = 0; nf < 4; nf++)
#pragma unroll
            for (int j = 0; j < 4; j++) acc[mf][nf][j] = 0.f;

    for (int s = 0; s < 3; s++) { g1_load(sbase, s, K0 + (size_t)s * KC, tid, mp, D0); CP_COMMIT(); }

    for (int k = 0; k < KITERS; k++) {
        CP_WAIT2();
        __syncthreads();
        if (k + 3 < KITERS)
            g1_load(sbase, (k + 3) & 3, K0 + (size_t)(k + 3) * KC, tid, mp, D0);
        CP_COMMIT();

        const float*    Af = sm + (k & 3) * A_STG;
        const uint32_t* Bf = reinterpret_cast<const uint32_t*>(sm + B_OFF + (k & 3) * B_STG);

#pragma unroll
        for (int ks = 0; ks < 2; ks++) {
            const float* Ar  = Af + (ks * 8 + lq) * AST;
            const float* Ar4 = Ar + 4 * AST;
            uint32_t au[2][4];
#pragma unroll
            for (int mf = 0; mf < 2; mf++) {
                int dw = wm * 32 + mf * 16 + lr;
                au[mf][0] = t32(Ar [dw]);
                au[mf][1] = t32(Ar [dw + 8]);
                au[mf][2] = t32(Ar4[dw]);
                au[mf][3] = t32(Ar4[dw + 8]);
            }
            const uint32_t* Br  = Bf + (ks * 8 + lq) * BST;
            const uint32_t* Br4 = Br + 4 * BST;
            uint32_t bu[4][2];
#pragma unroll
            for (int nf = 0; nf < 4; nf++) {
                int ew = wn * 32 + nf * 8 + lr;
                bu[nf][0] = Br [ew];
                bu[nf][1] = Br4[ew];
            }
#pragma unroll
            for (int mf = 0; mf < 2; mf++)
#pragma unroll
                for (int nf = 0; nf < 4; nf++)
                    mma_tf32(acc[mf][nf], au[mf], bu[nf]);
        }
    }

    float* outbase = g_A1 + (size_t)kh * CH;
#pragma unroll
    for (int mf = 0; mf < 2; mf++) {
        size_t r0 = D0 + (size_t)(wm * 32 + mf * 16 + lr);
#pragma unroll
        for (int nf = 0; nf < 4; nf++) {
            int e0 = wn * 32 + nf * 8 + 2 * lq;
            *reinterpret_cast<float2*>(&outbase[r0 * E_DIM + e0]) =
                make_float2(acc[mf][nf][0], acc[mf][nf][1]);
            *reinterpret_cast<float2*>(&outbase[(r0 + 8) * E_DIM + e0]) =
                make_float2(acc[mf][nf][2], acc[mf][nf][3]);
        }
    }
}

__global__ void __launch_bounds__(256)
g2_bpA1(const float* __restrict__ bp) {
    __shared__ float bps[128 * 36];
    __shared__ float a1s[32 * 68];
    int tid = threadIdx.x;
    int tx = tid & 15, ty = tid >> 4;
    size_t c0 = (size_t)blockIdx.x * 128;

    float acc[8][4];
#pragma unroll
    for (int i = 0; i < 8; i++)
#pragma unroll
        for (int j = 0; j < 4; j++) acc[i][j] = 0.f;

    for (int cc = 0; cc < 4; cc++) {
#pragma unroll
        for (int i = 0; i < 4; i++) {
            int q = tid + 256 * i;
            int row = q >> 3, c4 = q & 7;
            *reinterpret_cast<float4*>(&bps[row * 36 + c4 * 4]) =
                *reinterpret_cast<const float4*>(&bp[(size_t)row * C_DIM + c0 + cc * 32 + c4 * 4]);
        }
#pragma unroll
        for (int i = 0; i < 2; i++) {
            int q = tid + 256 * i;
            int row = q >> 4, c4 = q & 15;
            size_t gi = (c0 + cc * 32 + (size_t)row) * E_DIM + c4 * 4;
            float4 v0 = *reinterpret_cast<const float4*>(&g_A1[gi]);
            float4 v1 = *reinterpret_cast<const float4*>(&g_A1[CH + gi]);
            *reinterpret_cast<float4*>(&a1s[row * 68 + c4 * 4]) =
                make_float4(v0.x + v1.x, v0.y + v1.y, v0.z + v1.z, v0.w + v1.w);
        }
        __syncthreads();
#pragma unroll 4
        for (int c = 0; c < 32; c++) {
            float4 bv = *reinterpret_cast<const float4*>(&a1s[c * 68 + tx * 4]);
#pragma unroll
            for (int i = 0; i < 8; i++) {
                float a = bps[(ty * 8 + i) * 36 + c];
                acc[i][0] += a * bv.x; acc[i][1] += a * bv.y;
                acc[i][2] += a * bv.z; acc[i][3] += a * bv.w;
            }
        }
        __syncthreads();
    }
    float* op = g_part + (size_t)blockIdx.x * (B_DIM * E_DIM);
#pragma unroll
    for (int i = 0; i < 8; i++)
        *reinterpret_cast<float4*>(&op[(ty * 8 + i) * E_DIM + tx * 4]) =
            make_float4(acc[i][0], acc[i][1], acc[i][2], acc[i][3]);
}

__global__ void __launch_bounds__(128)
g3_out(const float* __restrict__ w, float* __restrict__ out) {
    __shared__ float zs[E_DIM];
    int b = blockIdx.x, t = threadIdx.x;
    if (t < E_DIM) {
        float s = 0.f;
#pragma unroll 8
        for (int p = 0; p < 128; p++)
            s += g_part[(size_t)p * (B_DIM * E_DIM) + b * E_DIM + t];
        zs[t] = s;
    }
    __syncthreads();
    float acc = 0.f;
#pragma unroll 8
    for (int e = 0; e < E_DIM; e++)
        acc += zs[e] * w[e * M_DIM + t];
    out[b * M_DIM + t] = acc;
}

extern "C" void kernel_launch(void* const* d_in, const int* in_sizes, int n_in,
                              void* d_out, int out_size) {
    const float* bp = (const float*)d_in[0];
    const float* mp = (const float*)d_in[1];
    const float* ce = (const float*)d_in[2];
    const float* w  = (const float*)d_in[3];
    float* out = (float*)d_out;

    cudaFuncSetAttribute(g1_mpce, cudaFuncAttributeMaxDynamicSharedMemorySize, SMEM_BYTES);

    k0_cvt<<<(C_DIM * E_DIM) / 1024, 256>>>(ce);
    g1_mpce<<<256, 256, SMEM_BYTES>>>(mp);
    g2_bpA1<<<128, 256>>>(bp);
    g3_out<<<128, 128>>>(w, out);
}

// round 5
// speedup vs baseline: 1.2565x; 1.0579x over previous
#include <cuda_runtime.h>
#include <cstdint>

// out[b,m] = einsum('bd,cd,ce,em->bm', bp, mp, CE, W)
//   K0 : CEt = tf32(CE)
//   G1 : A1[q][d,e] = sum_{c in quarter q} mp[c,d]*CE[c,e]   (tf32 mma.sync, K-split x4)
//   G2 : part[p][b,e] = bp[:,p-slab] @ (sum_q A1[q])[p-slab,:]
//   G3a: Z = sum_p part[p]     G3b: out = Z @ W
// B=128, C=16384, E=64, M=128 fp32.

#define C_DIM 16384
#define E_DIM 64
#define B_DIM 128
#define M_DIM 128

#define KSPLIT 4
#define KQ     (C_DIM / KSPLIT)   // 4096
#define KC     16
#define KITERS (KQ / KC)          // 256
#define DT     256                // d-tile per CTA
#define AST    264                // A smem row stride (256 + 8 pad)
#define BST    72                 // B smem row stride (64 + 8 pad)
#define A_STG  (KC * AST)         // 4224 floats
#define B_STG  (KC * BST)         // 1152 floats
#define NSTG   3
#define B_OFF  (NSTG * A_STG)
#define SMEM_BYTES ((NSTG * (A_STG + B_STG)) * 4)   // 64512 -> 2 CTAs/SM

#define CH ((size_t)C_DIM * E_DIM)

__device__ float    g_A1  [KSPLIT * CH];                  // 16 MB
__device__ uint32_t g_CEt [CH];                           // 4 MB
__device__ float    g_part[(size_t)128 * B_DIM * E_DIM];  // 4 MB
__device__ float    g_Z   [(size_t)B_DIM * E_DIM];

__device__ __forceinline__ uint32_t smem_u32(const void* p) {
    uint32_t a;
    asm("{ .reg .u64 t; cvta.to.shared.u64 t, %1; cvt.u32.u64 %0, t; }" : "=r"(a) : "l"(p));
    return a;
}
__device__ __forceinline__ void cp16(uint32_t s, const void* g) {
    asm volatile("cp.async.cg.shared.global [%0], [%1], 16;" :: "r"(s), "l"(g) : "memory");
}
#define CP_COMMIT() asm volatile("cp.async.commit_group;" ::: "memory")
#define CP_WAIT1()  asm volatile("cp.async.wait_group 1;" ::: "memory")

__device__ __forceinline__ uint32_t t32(float x) {
    uint32_t u;
    asm("cvt.rna.tf32.f32 %0, %1;" : "=r"(u) : "f"(x));
    return u;
}
__device__ __forceinline__ void mma_tf32(float* c, const uint32_t* a, const uint32_t* b) {
    asm volatile(
        "mma.sync.aligned.m16n8k8.row.col.f32.tf32.tf32.f32 "
        "{%0,%1,%2,%3}, {%4,%5,%6,%7}, {%8,%9}, {%0,%1,%2,%3};"
        : "+f"(c[0]), "+f"(c[1]), "+f"(c[2]), "+f"(c[3])
        : "r"(a[0]), "r"(a[1]), "r"(a[2]), "r"(a[3]), "r"(b[0]), "r"(b[1]));
}

// ---------------- K0 ----------------
__global__ void __launch_bounds__(256) k0_cvt(const float* __restrict__ ce) {
    size_t i = ((size_t)blockIdx.x * 256 + threadIdx.x) * 4;
    float4 v = *reinterpret_cast<const float4*>(ce + i);
    uint4 o;
    o.x = t32(v.x); o.y = t32(v.y); o.z = t32(v.z); o.w = t32(v.w);
    *reinterpret_cast<uint4*>(g_CEt + i) = o;
}

// ---------------- G1 ----------------
// CTA tile: 256(d) x 64(e), K per CTA = 4096. 8 warps as 4(d) x 2(e); warp 64x32.
__device__ __forceinline__ void g1_load(uint32_t sbase, int stage, size_t krow, int tid,
                                        const float* __restrict__ mp, size_t D0) {
    uint32_t sA = sbase + (uint32_t)(stage * A_STG) * 4u;
    uint32_t sB = sbase + (uint32_t)(B_OFF + stage * B_STG) * 4u;
#pragma unroll
    for (int i = 0; i < 4; i++) {                 // A: 16 rows x 1024 B
        int q = tid + 256 * i;                    // 0..1023
        int row = q >> 6, c16 = q & 63;
        cp16(sA + (uint32_t)(row * (AST * 4) + c16 * 16),
             mp + (krow + (size_t)row) * C_DIM + D0 + (size_t)c16 * 4);
    }
    {                                             // B: 16 rows x 256 B (tf32)
        int row = tid >> 4, c16 = tid & 15;
        cp16(sB + (uint32_t)(row * (BST * 4) + c16 * 16),
             g_CEt + (krow + (size_t)row) * E_DIM + (size_t)c16 * 4);
    }
}

__global__ void __launch_bounds__(256, 2)
g1_mpce(const float* __restrict__ mp) {
    extern __shared__ float sm[];
    uint32_t sbase = smem_u32(sm);
    const int tid  = threadIdx.x;
    const int wid  = tid >> 5, lane = tid & 31;
    const int lq   = lane & 3, lr = lane >> 2;
    const int wm   = wid >> 1;            // d offset wm*64
    const int wn   = wid & 1;             // e offset wn*32
    const int slab = blockIdx.x & 63;
    const int kh   = blockIdx.x >> 6;     // 0..3
    const size_t D0 = (size_t)slab * DT;
    const size_t K0 = (size_t)kh * KQ;

    float acc[4][4][4];
#pragma unroll
    for (int mf = 0; mf < 4; mf++)
#pragma unroll
        for (int nf = 0; nf < 4; nf++)
#pragma unroll
            for (int j = 0; j < 4; j++) acc[mf][nf][j] = 0.f;

    g1_load(sbase, 0, K0, tid, mp, D0);            CP_COMMIT();
    g1_load(sbase, 1, K0 + KC, tid, mp, D0);       CP_COMMIT();

    int stage = 0;
    for (int k = 0; k < KITERS; k++) {
        CP_WAIT1();
        __syncthreads();
        if (k + 2 < KITERS) {
            int ns = stage + 2; if (ns >= NSTG) ns -= NSTG;
            g1_load(sbase, ns, K0 + (size_t)(k + 2) * KC, tid, mp, D0);
        }
        CP_COMMIT();

        const float*    Af = sm + stage * A_STG;
        const uint32_t* Bf = reinterpret_cast<const uint32_t*>(sm + B_OFF + stage * B_STG);

#pragma unroll
        for (int ks = 0; ks < 2; ks++) {
            const float* Ar  = Af + (ks * 8 + lq) * AST;
            const float* Ar4 = Ar + 4 * AST;
            uint32_t au[4][4];
#pragma unroll
            for (int mf = 0; mf < 4; mf++) {
                int dw = wm * 64 + mf * 16 + lr;
                au[mf][0] = t32(Ar [dw]);
                au[mf][1] = t32(Ar [dw + 8]);
                au[mf][2] = t32(Ar4[dw]);
                au[mf][3] = t32(Ar4[dw + 8]);
            }
            const uint32_t* Br  = Bf + (ks * 8 + lq) * BST;
            const uint32_t* Br4 = Br + 4 * BST;
            uint32_t bu[4][2];
#pragma unroll
            for (int nf = 0; nf < 4; nf++) {
                int ew = wn * 32 + nf * 8 + lr;
                bu[nf][0] = Br [ew];
                bu[nf][1] = Br4[ew];
            }
#pragma unroll
            for (int mf = 0; mf < 4; mf++)
#pragma unroll
                for (int nf = 0; nf < 4; nf++)
                    mma_tf32(acc[mf][nf], au[mf], bu[nf]);
        }
        stage = (stage + 1 == NSTG) ? 0 : stage + 1;
    }

    float* outbase = g_A1 + (size_t)kh * CH;
#pragma unroll
    for (int mf = 0; mf < 4; mf++) {
        size_t r0 = D0 + (size_t)(wm * 64 + mf * 16 + lr);
#pragma unroll
        for (int nf = 0; nf < 4; nf++) {
            int e0 = wn * 32 + nf * 8 + 2 * lq;
            *reinterpret_cast<float2*>(&outbase[r0 * E_DIM + e0]) =
                make_float2(acc[mf][nf][0], acc[mf][nf][1]);
            *reinterpret_cast<float2*>(&outbase[(r0 + 8) * E_DIM + e0]) =
                make_float2(acc[mf][nf][2], acc[mf][nf][3]);
        }
    }
}

// ---------------- G2 ----------------
__global__ void __launch_bounds__(256)
g2_bpA1(const float* __restrict__ bp) {
    __shared__ float bps[128 * 36];
    __shared__ float a1s[32 * 68];
    int tid = threadIdx.x;
    int tx = tid & 15, ty = tid >> 4;
    size_t c0 = (size_t)blockIdx.x * 128;

    float acc[8][4];
#pragma unroll
    for (int i = 0; i < 8; i++)
#pragma unroll
        for (int j = 0; j < 4; j++) acc[i][j] = 0.f;

    for (int cc = 0; cc < 4; cc++) {
#pragma unroll
        for (int i = 0; i < 4; i++) {
            int q = tid + 256 * i;
            int row = q >> 3, c4 = q & 7;
            *reinterpret_cast<float4*>(&bps[row * 36 + c4 * 4]) =
                *reinterpret_cast<const float4*>(&bp[(size_t)row * C_DIM + c0 + cc * 32 + c4 * 4]);
        }
#pragma unroll
        for (int i = 0; i < 2; i++) {
            int q = tid + 256 * i;
            int row = q >> 4, c4 = q & 15;
            size_t gi = (c0 + cc * 32 + (size_t)row) * E_DIM + c4 * 4;
            float4 v0 = *reinterpret_cast<const float4*>(&g_A1[gi]);
            float4 v1 = *reinterpret_cast<const float4*>(&g_A1[CH + gi]);
            float4 v2 = *reinterpret_cast<const float4*>(&g_A1[2 * CH + gi]);
            float4 v3 = *reinterpret_cast<const float4*>(&g_A1[3 * CH + gi]);
            *reinterpret_cast<float4*>(&a1s[row * 68 + c4 * 4]) =
                make_float4((v0.x + v1.x) + (v2.x + v3.x),
                            (v0.y + v1.y) + (v2.y + v3.y),
                            (v0.z + v1.z) + (v2.z + v3.z),
                            (v0.w + v1.w) + (v2.w + v3.w));
        }
        __syncthreads();
#pragma unroll 4
        for (int c = 0; c < 32; c++) {
            float4 bv = *reinterpret_cast<const float4*>(&a1s[c * 68 + tx * 4]);
#pragma unroll
            for (int i = 0; i < 8; i++) {
                float a = bps[(ty * 8 + i) * 36 + c];
                acc[i][0] += a * bv.x; acc[i][1] += a * bv.y;
                acc[i][2] += a * bv.z; acc[i][3] += a * bv.w;
            }
        }
        __syncthreads();
    }
    float* op = g_part + (size_t)blockIdx.x * (B_DIM * E_DIM);
#pragma unroll
    for (int i = 0; i < 8; i++)
        *reinterpret_cast<float4*>(&op[(ty * 8 + i) * E_DIM + tx * 4]) =
            make_float4(acc[i][0], acc[i][1], acc[i][2], acc[i][3]);
}

// ---------------- G3a: Z = sum_p part[p] (coalesced) ----------------
__global__ void __launch_bounds__(256)
g3a_reduce() {
    int idx = blockIdx.x * 256 + threadIdx.x;   // 0..8191
    float s = 0.f;
#pragma unroll 8
    for (int p = 0; p < 128; p++)
        s += g_part[(size_t)p * (B_DIM * E_DIM) + idx];
    g_Z[idx] = s;
}

// ---------------- G3b: out = Z @ W ----------------
__global__ void __launch_bounds__(128)
g3b_out(const float* __restrict__ w, float* __restrict__ out) {
    __shared__ float zs[E_DIM];
    int b = blockIdx.x, t = threadIdx.x;
    if (t < E_DIM) zs[t] = g_Z[b * E_DIM + t];
    __syncthreads();
    float acc = 0.f;
#pragma unroll 8
    for (int e = 0; e < E_DIM; e++)
        acc += zs[e] * w[e * M_DIM + t];
    out[b * M_DIM + t] = acc;
}

// ---------------- launch ----------------
extern "C" void kernel_launch(void* const* d_in, const int* in_sizes, int n_in,
                              void* d_out, int out_size) {
    const float* bp = (const float*)d_in[0];
    const float* mp = (const float*)d_in[1];
    const float* ce = (const float*)d_in[2];
    const float* w  = (const float*)d_in[3];
    float* out = (float*)d_out;

    cudaFuncSetAttribute(g1_mpce, cudaFuncAttributeMaxDynamicSharedMemorySize, SMEM_BYTES);

    k0_cvt<<<(C_DIM * E_DIM) / 1024, 256>>>(ce);
    g1_mpce<<<64 * KSPLIT, 256, SMEM_BYTES>>>(mp);
    g2_bpA1<<<128, 256>>>(bp);
    g3a_reduce<<<B_DIM * E_DIM / 256, 256>>>();
    g3b_out<<<B_DIM, M_DIM>>>(w, out);
}

// round 6
// speedup vs baseline: 1.5199x; 1.2097x over previous
#include <cuda_runtime.h>
#include <cstdint>

// out[b,m] = einsum('bd,cd,ce,em->bm', bp, mp, CE, W)
//   K0 : CEh[e][c] = fp16(CE[c][e])   (convert + transpose, 2 MB)
//   G1 : A1[q][d,e] = sum_{c in quarter q} mp[c,d]*CE[c,e]   (fp16 mma.sync m16n8k16, fp32 acc)
//   G2 : part[p][b,e] = bp[:,p-slab] @ (sum_q A1[q])[p-slab,:]
//   G3a: Z2[chunk] = partial sums   G3b: out = Z @ W
// B=128, C=16384, E=64, M=128 fp32.

#define C_DIM 16384
#define E_DIM 64
#define B_DIM 128
#define M_DIM 128

#define KSPLIT 4
#define KQ     (C_DIM / KSPLIT)   // 4096
#define KC     16
#define KITERS (KQ / KC)          // 256
#define DT     256                // d-tile per CTA

#define AST    260                // A smem row stride in floats (256 + 4) -> bank-safe for fp16 frags
#define A_ROW_B (AST * 4)         // 1040 bytes
#define A_STG_F (KC * AST)        // 4160 floats
#define A_STG_B (KC * A_ROW_B)    // 16640 bytes
#define BSTH   24                 // B smem row stride in fp16 (16 + 8)
#define B_STG_B (E_DIM * BSTH * 2)  // 3072 bytes
#define NSTG   4
#define B_OFF_B (NSTG * A_STG_B)    // 66560
#define SMEM_BYTES (B_OFF_B + NSTG * B_STG_B)   // 78848 -> 2 CTAs/SM

#define CH ((size_t)C_DIM * E_DIM)

__device__ float    g_A1  [KSPLIT * CH];                  // 16 MB
__device__ uint16_t g_CEh [CH];                           // 2 MB fp16, [e][c]
__device__ float    g_part[(size_t)128 * B_DIM * E_DIM];  // 4 MB
__device__ float    g_Z2  [4 * (size_t)B_DIM * E_DIM];

// ---------------- helpers ----------------
__device__ __forceinline__ uint32_t smem_u32(const void* p) {
    uint32_t a;
    asm("{ .reg .u64 t; cvta.to.shared.u64 t, %1; cvt.u32.u64 %0, t; }" : "=r"(a) : "l"(p));
    return a;
}
__device__ __forceinline__ void cp16(uint32_t s, const void* g) {
    asm volatile("cp.async.cg.shared.global [%0], [%1], 16;" :: "r"(s), "l"(g) : "memory");
}
#define CP_COMMIT() asm volatile("cp.async.commit_group;" ::: "memory")
#define CP_WAIT2()  asm volatile("cp.async.wait_group 2;" ::: "memory")

// pack two fp32 -> f16x2 reg: lo half = first arg
__device__ __forceinline__ uint32_t pk16(float lo, float hi) {
    uint32_t r;
    asm("cvt.rn.f16x2.f32 %0, %1, %2;" : "=r"(r) : "f"(hi), "f"(lo));
    return r;
}
__device__ __forceinline__ void mma_f16(float* c, const uint32_t* a, const uint32_t* b) {
    asm volatile(
        "mma.sync.aligned.m16n8k16.row.col.f32.f16.f16.f32 "
        "{%0,%1,%2,%3}, {%4,%5,%6,%7}, {%8,%9}, {%0,%1,%2,%3};"
        : "+f"(c[0]), "+f"(c[1]), "+f"(c[2]), "+f"(c[3])
        : "r"(a[0]), "r"(a[1]), "r"(a[2]), "r"(a[3]), "r"(b[0]), "r"(b[1]));
}

// ---------------- K0: CEh[e][c] = fp16(CE[c][e]) ----------------
__global__ void __launch_bounds__(256) k0_cvt(const float* __restrict__ ce) {
    int idx = blockIdx.x * 256 + threadIdx.x;   // 0..131071
    int e  = idx >> 11;                         // 0..63
    int c0 = (idx & 2047) << 3;                 // 0..16376 step 8
    uint32_t r[4];
#pragma unroll
    for (int j = 0; j < 4; j++) {
        float v0 = __ldg(ce + (size_t)(c0 + 2*j)     * E_DIM + e);
        float v1 = __ldg(ce + (size_t)(c0 + 2*j + 1) * E_DIM + e);
        r[j] = pk16(v0, v1);
    }
    *reinterpret_cast<uint4*>(g_CEh + (size_t)e * C_DIM + c0) =
        make_uint4(r[0], r[1], r[2], r[3]);
}

// ---------------- G1 ----------------
// CTA tile: 256(d) x 64(e), K per CTA = 4096. 8 warps as 4(d) x 2(e); warp 64x32.
__device__ __forceinline__ void g1_load(uint32_t sbase, int stage, size_t krow, int tid,
                                        const float* __restrict__ mp, size_t D0) {
    uint32_t sA = sbase + (uint32_t)(stage * A_STG_B);
    uint32_t sB = sbase + (uint32_t)(B_OFF_B + stage * B_STG_B);
#pragma unroll
    for (int i = 0; i < 4; i++) {                 // A: 16 rows x 1024 B (fp32)
        int q = tid + 256 * i;                    // 0..1023
        int row = q >> 6, c16 = q & 63;
        cp16(sA + (uint32_t)(row * A_ROW_B + c16 * 16),
             mp + (krow + (size_t)row) * C_DIM + D0 + (size_t)c16 * 4);
    }
    if (tid < 128) {                              // B: 64 e-rows x 32 B (fp16)
        int e = tid >> 1, h = tid & 1;
        cp16(sB + (uint32_t)(e * (BSTH * 2) + h * 16),
             g_CEh + (size_t)e * C_DIM + krow + (size_t)h * 8);
    }
}

__global__ void __launch_bounds__(256, 2)
g1_mpce(const float* __restrict__ mp) {
    extern __shared__ float sm[];
    uint32_t sbase = smem_u32(sm);
    const int tid  = threadIdx.x;
    const int wid  = tid >> 5, lane = tid & 31;
    const int lq   = lane & 3, lr = lane >> 2;
    const int wm   = wid >> 1;            // d offset wm*64
    const int wn   = wid & 1;             // e offset wn*32
    const int slab = blockIdx.x & 63;
    const int kh   = blockIdx.x >> 6;     // 0..3
    const size_t D0 = (size_t)slab * DT;
    const size_t K0 = (size_t)kh * KQ;

    float acc[4][4][4];
#pragma unroll
    for (int mf = 0; mf < 4; mf++)
#pragma unroll
        for (int nf = 0; nf < 4; nf++)
#pragma unroll
            for (int j = 0; j < 4; j++) acc[mf][nf][j] = 0.f;

    g1_load(sbase, 0, K0,          tid, mp, D0); CP_COMMIT();
    g1_load(sbase, 1, K0 + KC,     tid, mp, D0); CP_COMMIT();
    g1_load(sbase, 2, K0 + 2 * KC, tid, mp, D0); CP_COMMIT();

    int stage = 0;
    for (int k = 0; k < KITERS; k++) {
        CP_WAIT2();
        __syncthreads();
        if (k + 3 < KITERS) {
            int ns = stage + 3; if (ns >= NSTG) ns -= NSTG;
            g1_load(sbase, ns, K0 + (size_t)(k + 3) * KC, tid, mp, D0);
        }
        CP_COMMIT();

        const float*    Af = sm + stage * A_STG_F;
        const uint16_t* Bh = reinterpret_cast<const uint16_t*>(
            reinterpret_cast<const char*>(sm) + B_OFF_B + stage * B_STG_B);

        const float* Ak0 = Af + (2 * lq) * AST;       // k = 2lq
        const float* Ak1 = Ak0 + AST;                 // k = 2lq+1
        const float* Ak8 = Ak0 + 8 * AST;             // k = 2lq+8
        const float* Ak9 = Ak8 + AST;                 // k = 2lq+9

        uint32_t au[4][4];
#pragma unroll
        for (int mf = 0; mf < 4; mf++) {
            int dw = wm * 64 + mf * 16 + lr;
            au[mf][0] = pk16(Ak0[dw],     Ak1[dw]);
            au[mf][1] = pk16(Ak0[dw + 8], Ak1[dw + 8]);
            au[mf][2] = pk16(Ak8[dw],     Ak9[dw]);
            au[mf][3] = pk16(Ak8[dw + 8], Ak9[dw + 8]);
        }
        uint32_t bu[4][2];
#pragma unroll
        for (int nf = 0; nf < 4; nf++) {
            int ew = wn * 32 + nf * 8 + lr;
            bu[nf][0] = *reinterpret_cast<const uint32_t*>(Bh + ew * BSTH + 2 * lq);
            bu[nf][1] = *reinterpret_cast<const uint32_t*>(Bh + ew * BSTH + 2 * lq + 8);
        }
#pragma unroll
        for (int mf = 0; mf < 4; mf++)
#pragma unroll
            for (int nf = 0; nf < 4; nf++)
                mma_f16(acc[mf][nf], au[mf], bu[nf]);

        stage = (stage + 1 == NSTG) ? 0 : stage + 1;
    }

    float* outbase = g_A1 + (size_t)kh * CH;
#pragma unroll
    for (int mf = 0; mf < 4; mf++) {
        size_t r0 = D0 + (size_t)(wm * 64 + mf * 16 + lr);
#pragma unroll
        for (int nf = 0; nf < 4; nf++) {
            int e0 = wn * 32 + nf * 8 + 2 * lq;
            *reinterpret_cast<float2*>(&outbase[r0 * E_DIM + e0]) =
                make_float2(acc[mf][nf][0], acc[mf][nf][1]);
            *reinterpret_cast<float2*>(&outbase[(r0 + 8) * E_DIM + e0]) =
                make_float2(acc[mf][nf][2], acc[mf][nf][3]);
        }
    }
}

// ---------------- G2 ----------------
__global__ void __launch_bounds__(256)
g2_bpA1(const float* __restrict__ bp) {
    __shared__ float bps[128 * 36];
    __shared__ float a1s[32 * 68];
    int tid = threadIdx.x;
    int tx = tid & 15, ty = tid >> 4;
    size_t c0 = (size_t)blockIdx.x * 128;

    float acc[8][4];
#pragma unroll
    for (int i = 0; i < 8; i++)
#pragma unroll
        for (int j = 0; j < 4; j++) acc[i][j] = 0.f;

    for (int cc = 0; cc < 4; cc++) {
#pragma unroll
        for (int i = 0; i < 4; i++) {
            int q = tid + 256 * i;
            int row = q >> 3, c4 = q & 7;
            *reinterpret_cast<float4*>(&bps[row * 36 + c4 * 4]) =
                *reinterpret_cast<const float4*>(&bp[(size_t)row * C_DIM + c0 + cc * 32 + c4 * 4]);
        }
#pragma unroll
        for (int i = 0; i < 2; i++) {
            int q = tid + 256 * i;
            int row = q >> 4, c4 = q & 15;
            size_t gi = (c0 + cc * 32 + (size_t)row) * E_DIM + c4 * 4;
            float4 v0 = *reinterpret_cast<const float4*>(&g_A1[gi]);
            float4 v1 = *reinterpret_cast<const float4*>(&g_A1[CH + gi]);
            float4 v2 = *reinterpret_cast<const float4*>(&g_A1[2 * CH + gi]);
            float4 v3 = *reinterpret_cast<const float4*>(&g_A1[3 * CH + gi]);
            *reinterpret_cast<float4*>(&a1s[row * 68 + c4 * 4]) =
                make_float4((v0.x + v1.x) + (v2.x + v3.x),
                            (v0.y + v1.y) + (v2.y + v3.y),
                            (v0.z + v1.z) + (v2.z + v3.z),
                            (v0.w + v1.w) + (v2.w + v3.w));
        }
        __syncthreads();
#pragma unroll 4
        for (int c = 0; c < 32; c++) {
            float4 bv = *reinterpret_cast<const float4*>(&a1s[c * 68 + tx * 4]);
#pragma unroll
            for (int i = 0; i < 8; i++) {
                float a = bps[(ty * 8 + i) * 36 + c];
                acc[i][0] += a * bv.x; acc[i][1] += a * bv.y;
                acc[i][2] += a * bv.z; acc[i][3] += a * bv.w;
            }
        }
        __syncthreads();
    }
    float* op = g_part + (size_t)blockIdx.x * (B_DIM * E_DIM);
#pragma unroll
    for (int i = 0; i < 8; i++)
        *reinterpret_cast<float4*>(&op[(ty * 8 + i) * E_DIM + tx * 4]) =
            make_float4(acc[i][0], acc[i][1], acc[i][2], acc[i][3]);
}

// ---------------- G3a: chunked reduce (4 chunks x 32 partials) ----------------
__global__ void __launch_bounds__(256)
g3a_reduce() {
    int chunk = blockIdx.x >> 5;                           // 0..3
    int be = ((blockIdx.x & 31) << 8) + threadIdx.x;       // 0..8191
    const float* p = g_part + (size_t)chunk * 32 * (B_DIM * E_DIM) + be;
    float s = 0.f;
#pragma unroll 8
    for (int i = 0; i < 32; i++)
        s += p[(size_t)i * (B_DIM * E_DIM)];
    g_Z2[(size_t)chunk * (B_DIM * E_DIM) + be] = s;
}

// ---------------- G3b: out = Z @ W ----------------
__global__ void __launch_bounds__(128)
g3b_out(const float* __restrict__ w, float* __restrict__ out) {
    __shared__ float zs[E_DIM];
    int b = blockIdx.x, t = threadIdx.x;
    if (t < E_DIM) {
        int be = b * E_DIM + t;
        zs[t] = (g_Z2[be] + g_Z2[(B_DIM * E_DIM) + be]) +
                (g_Z2[2 * (B_DIM * E_DIM) + be] + g_Z2[3 * (B_DIM * E_DIM) + be]);
    }
    __syncthreads();
    float acc = 0.f;
#pragma unroll 8
    for (int e = 0; e < E_DIM; e++)
        acc += zs[e] * w[e * M_DIM + t];
    out[b * M_DIM + t] = acc;
}

// ---------------- launch ----------------
extern "C" void kernel_launch(void* const* d_in, const int* in_sizes, int n_in,
                              void* d_out, int out_size) {
    const float* bp = (const float*)d_in[0];
    const float* mp = (const float*)d_in[1];
    const float* ce = (const float*)d_in[2];
    const float* w  = (const float*)d_in[3];
    float* out = (float*)d_out;

    cudaFuncSetAttribute(g1_mpce, cudaFuncAttributeMaxDynamicSharedMemorySize, SMEM_BYTES);

    k0_cvt<<<512, 256>>>(ce);
    g1_mpce<<<64 * KSPLIT, 256, SMEM_BYTES>>>(mp);
    g2_bpA1<<<128, 256>>>(bp);
    g3a_reduce<<<128, 256>>>();
    g3b_out<<<B_DIM, M_DIM>>>(w, out);
}